// round 10
// baseline (speedup 1.0000x reference)
#include <cuda_runtime.h>

typedef unsigned long long u64;

#define LH 150
#define KI 10
#define NWARP 16

// ---- packed f32x2 helpers -------------------------------------------------
__device__ __forceinline__ u64 fma2(u64 a, u64 b, u64 c) {
    u64 d;
    asm("fma.rn.f32x2 %0, %1, %2, %3;" : "=l"(d) : "l"(a), "l"(b), "l"(c));
    return d;
}
__device__ __forceinline__ u64 pack2(float lo, float hi) {
    u64 r;
    asm("mov.b64 %0, {%1, %2};" : "=l"(r) : "f"(lo), "f"(hi));
    return r;
}
__device__ __forceinline__ u64 splat2(float x) {
    u64 r;
    asm("mov.b64 %0, {%1, %1};" : "=l"(r) : "f"(x));
    return r;
}
__device__ __forceinline__ float2 unpack2(u64 p) {
    float2 v;
    asm("mov.b64 {%0, %1}, %2;" : "=f"(v.x), "=f"(v.y) : "l"(p));
    return v;
}

// Single-level stencil: lane l = (y=l>>3, x=l&7) owns vA=v(2y,x), vB=v(2y+1,x).
// Every halo tap is ONE shuffle of the original vA/vB (10 independent shfls,
// critical path = 1 shuffle), boundary zeros applied post-shuffle:
//   A north row (2y-1) = vB of lane-8 (cols via lane-9/-8/-7)
//   B south row (2y+2) = vA of lane+8 (cols via lane+7/+8/+9)
//   mid rows W/E       = vA/vB of lane+-1
// fv[12] = {NW,N,NE, WA,vA,EA, WB,vB,EB, SW,S,SE};
// pixel A tap k uses fv[k], pixel B tap k uses fv[k+3].
__device__ __forceinline__ void stencil10(float vA, float vB,
                                          int lNW, int lN, int lNE,
                                          int lW, int lE,
                                          int lSW, int lS, int lSE,
                                          bool hn, bool hs, bool hw, bool he,
                                          float* fv) {
    const unsigned m = 0xffffffffu;
    float tNW = __shfl_sync(m, vB, lNW);
    float tN  = __shfl_sync(m, vB, lN);
    float tNE = __shfl_sync(m, vB, lNE);
    float tWA = __shfl_sync(m, vA, lW);
    float tEA = __shfl_sync(m, vA, lE);
    float tWB = __shfl_sync(m, vB, lW);
    float tEB = __shfl_sync(m, vB, lE);
    float tSW = __shfl_sync(m, vA, lSW);
    float tS  = __shfl_sync(m, vA, lS);
    float tSE = __shfl_sync(m, vA, lSE);
    fv[0] = (hn && hw) ? tNW : 0.f;
    fv[1] = hn ? tN : 0.f;
    fv[2] = (hn && he) ? tNE : 0.f;
    fv[3] = hw ? tWA : 0.f;
    fv[4] = vA;
    fv[5] = he ? tEA : 0.f;
    fv[6] = hw ? tWB : 0.f;
    fv[7] = vB;
    fv[8] = he ? tEB : 0.f;
    fv[9] = (hs && hw) ? tSW : 0.f;
    fv[10] = hs ? tS : 0.f;
    fv[11] = (hs && he) ? tSE : 0.f;
}

// One warp per batch element. c2-outer accumulation (4 live accumulators),
// 27 of 45 packed weights register-resident, other 18 re-read per sweep from
// SMEM via an opaque pointer -> regs <= 128 -> 512-thread blocks (4 w/SMSP).
__global__ __launch_bounds__(NWARP * 32)
void vin_kernel(const float* __restrict__ S,
                const float* __restrict__ Wh,
                const float* __restrict__ bh,
                const float* __restrict__ Wr,
                const float* __restrict__ Wq,
                const float* __restrict__ w,
                const float* __restrict__ Wfc,
                float* __restrict__ out, int B) {
    __shared__ float sweff[10];
    __shared__ u64 wsh[45];    // packed transition weights {w[2c2][k], w[2c2+1][k]}
    __shared__ u64 wqsh[45];   // packed Wq, same layout
    __shared__ float sfc[80];  // Wfc[8][10]

    const int tid = threadIdx.x;
    const int warp = tid >> 5;
    const int lane = tid & 31;

    // One-time staging of packed weights + FC head
    if (tid < 45) {
        const int c2 = tid / 9, k = tid % 9;
        wsh[tid] = pack2(__ldg(&w[(2 * c2) * 9 + k]),
                         __ldg(&w[(2 * c2 + 1) * 9 + k]));
    } else if (tid < 90) {
        const int t = tid - 45;
        const int c2 = t / 9, k = t % 9;
        wqsh[t] = pack2(__ldg(&Wq[(2 * c2) * 9 + k]),
                        __ldg(&Wq[(2 * c2 + 1) * 9 + k]));
    } else if (tid < 170) {
        sfc[tid - 90] = __ldg(&Wfc[tid - 90]);
    }
    // weff: collapse 150-ch hidden conv + 1x1 readout (warp j -> output j)
    if (warp < 10) {
        float acc = 0.f;
        for (int c = lane; c < LH; c += 32) {
            float x = (warp < 9) ? __ldg(&Wh[c * 9 + warp]) : __ldg(&bh[c]);
            acc = fmaf(__ldg(&Wr[c]), x, acc);
        }
#pragma unroll
        for (int off = 16; off >= 1; off >>= 1)
            acc += __shfl_xor_sync(0xffffffffu, acc, off);
        if (lane == 0) sweff[warp] = acc;
    }
    __syncthreads();

    const int b = blockIdx.x * NWARP + warp;
    if (b >= B) return;                    // warp-uniform; no syncs below
    const float* Sb = S + (long long)b * 66;

    const int y0 = lane >> 3, x0 = lane & 7;
    const int lNW = (lane + 23) & 31, lN = (lane + 24) & 31, lNE = (lane + 25) & 31;
    const int lW = (lane + 31) & 31, lE = (lane + 1) & 31;
    const int lSW = (lane + 7) & 31, lS = (lane + 8) & 31, lSE = (lane + 9) & 31;
    const bool hn = (y0 != 0), hs = (y0 != 3), hw = (x0 != 0), he = (x0 != 7);

    // Register-resident weights for c2 = 0..2 (54 regs)
    u64 wreg[27];
#pragma unroll
    for (int i = 0; i < 27; ++i) wreg[i] = wsh[i];

    // X in registers: vA = row 2y, vB = row 2y+1 of column x
    float vA = Sb[16 * y0 + x0];
    float vB = Sb[16 * y0 + 8 + x0];
    const int s1i = (int)Sb[64];
    const int s2i = (int)Sb[65];

    float fv[12];
    u64 su[12];

    // r = conv(X, W_eff, pad=1) + b_eff
    stencil10(vA, vB, lNW, lN, lNE, lW, lE, lSW, lS, lSE, hn, hs, hw, he, fv);
    float r0 = sweff[9], r1 = r0;
#pragma unroll
    for (int k = 0; k < 9; ++k) {
        r0 = fmaf(sweff[k], fv[k], r0);
        r1 = fmaf(sweff[k], fv[k + 3], r1);
    }

    // qr[c] = conv(r, Wq[c], pad=1)  (loop-invariant), c2-outer
    u64 qr0p[5], qr1p[5];
    stencil10(r0, r1, lNW, lN, lNE, lW, lE, lSW, lS, lSE, hn, hs, hw, he, fv);
#pragma unroll
    for (int j = 0; j < 12; ++j) su[j] = splat2(fv[j]);
#pragma unroll
    for (int c2 = 0; c2 < 5; ++c2) {
        u64 a0 = 0ull, a1 = 0ull;
#pragma unroll
        for (int k = 0; k < 9; ++k) {
            const u64 wq = wqsh[c2 * 9 + k];          // broadcast LDS, one-time
            a0 = fma2(wq, su[k], a0);
            a1 = fma2(wq, su[k + 3], a1);
        }
        qr0p[c2] = a0; qr1p[c2] = a1;
    }

    // v = max_c qr
    {
        float2 t0 = unpack2(qr0p[0]), t1 = unpack2(qr1p[0]);
        vA = fmaxf(t0.x, t0.y); vB = fmaxf(t1.x, t1.y);
#pragma unroll
        for (int c2 = 1; c2 < 5; ++c2) {
            t0 = unpack2(qr0p[c2]); t1 = unpack2(qr1p[c2]);
            vA = fmaxf(vA, fmaxf(t0.x, t0.y));
            vB = fmaxf(vB, fmaxf(t1.x, t1.y));
        }
    }

    // K-1 = 9 sweeps: v <- max_c( qr[c] + conv(v, w[c]) )
#pragma unroll 1
    for (int it = 0; it < KI - 1; ++it) {
        stencil10(vA, vB, lNW, lN, lNE, lW, lE, lSW, lS, lSE, hn, hs, hw, he, fv);
#pragma unroll
        for (int j = 0; j < 12; ++j) su[j] = splat2(fv[j]);
        // Opaque pointer: the 18 c2={3,4} weight loads stay per-sweep LDS
        // (not hoisted into registers), keeping regs <= 128.
        const u64* wdy = wsh + 27;
        asm("" : "+l"(wdy));
        float m0, m1;
#pragma unroll
        for (int c2 = 0; c2 < 5; ++c2) {
            u64 a0 = qr0p[c2], a1 = qr1p[c2];
#pragma unroll
            for (int k = 0; k < 9; ++k) {
                const u64 wk = (c2 < 3) ? wreg[c2 * 9 + k]
                                        : wdy[(c2 - 3) * 9 + k];
                a0 = fma2(wk, su[k], a0);
                a1 = fma2(wk, su[k + 3], a1);
            }
            const float2 t0 = unpack2(a0), t1 = unpack2(a1);
            const float mm0 = fmaxf(t0.x, t0.y), mm1 = fmaxf(t1.x, t1.y);
            m0 = c2 ? fmaxf(m0, mm0) : mm0;
            m1 = c2 ? fmaxf(m1, mm1) : mm1;
        }
        vA = m0; vB = m1;
    }

    // Final q only for the half containing the selected pixel (warp-uniform).
    stencil10(vA, vB, lNW, lN, lNE, lW, lE, lSW, lS, lSE, hn, hs, hw, he, fv);
#pragma unroll
    for (int j = 0; j < 12; ++j) su[j] = splat2(fv[j]);
    u64 accp[5];
    if (s1i & 1) {      // pixel in B half: taps su[k+3], base qr1p
#pragma unroll
        for (int c2 = 0; c2 < 5; ++c2) {
            u64 a = qr1p[c2];
#pragma unroll
            for (int k = 0; k < 9; ++k) {
                const u64 wk = (c2 < 3) ? wreg[c2 * 9 + k] : wsh[c2 * 9 + k];
                a = fma2(wk, su[k + 3], a);
            }
            accp[c2] = a;
        }
    } else {            // pixel in A half: taps su[k], base qr0p
#pragma unroll
        for (int c2 = 0; c2 < 5; ++c2) {
            u64 a = qr0p[c2];
#pragma unroll
            for (int k = 0; k < 9; ++k) {
                const u64 wk = (c2 < 3) ? wreg[c2 * 9 + k] : wsh[c2 * 9 + k];
                a = fma2(wk, su[k], a);
            }
            accp[c2] = a;
        }
    }

    // Selected pixel (s1=row, s2=col) lives in lane (s1>>1)*8 + s2.
    const int lsel = (s1i >> 1) * 8 + s2i;
    if (lane == lsel) {
        float lg[8];
#pragma unroll
        for (int j = 0; j < 8; ++j) lg[j] = 0.f;
#pragma unroll
        for (int c2 = 0; c2 < 5; ++c2) {
            const float2 q = unpack2(accp[c2]);
#pragma unroll
            for (int j = 0; j < 8; ++j) {
                lg[j] = fmaf(q.x, sfc[j * 10 + 2 * c2], lg[j]);
                lg[j] = fmaf(q.y, sfc[j * 10 + 2 * c2 + 1], lg[j]);
            }
        }
        float4* o4 = (float4*)(out + (long long)b * 8);
        o4[0] = make_float4(lg[0], lg[1], lg[2], lg[3]);
        o4[1] = make_float4(lg[4], lg[5], lg[6], lg[7]);
    }
}

extern "C" void kernel_launch(void* const* d_in, const int* in_sizes, int n_in,
                              void* d_out, int out_size) {
    const float* S   = (const float*)d_in[0];
    const float* Wh  = (const float*)d_in[1];
    const float* bh  = (const float*)d_in[2];
    const float* Wr  = (const float*)d_in[3];
    const float* Wq  = (const float*)d_in[4];
    const float* w   = (const float*)d_in[5];
    const float* Wfc = (const float*)d_in[6];
    float* out = (float*)d_out;

    const int B = in_sizes[0] / 66;
    const int grid = (B + NWARP - 1) / NWARP;
    vin_kernel<<<grid, NWARP * 32>>>(S, Wh, bh, Wr, Wq, w, Wfc, out, B);
}

// round 11
// speedup vs baseline: 1.0667x; 1.0667x over previous
#include <cuda_runtime.h>

typedef unsigned long long u64;

#define LH 150
#define KI 10
#define NWARP 12

// ---- packed f32x2 helpers -------------------------------------------------
__device__ __forceinline__ u64 fma2(u64 a, u64 b, u64 c) {
    u64 d;
    asm("fma.rn.f32x2 %0, %1, %2, %3;" : "=l"(d) : "l"(a), "l"(b), "l"(c));
    return d;
}
__device__ __forceinline__ u64 pack2(float lo, float hi) {
    u64 r;
    asm("mov.b64 %0, {%1, %2};" : "=l"(r) : "f"(lo), "f"(hi));
    return r;
}
__device__ __forceinline__ u64 splat2(float x) {
    u64 r;
    asm("mov.b64 %0, {%1, %1};" : "=l"(r) : "f"(x));
    return r;
}
__device__ __forceinline__ float2 unpack2(u64 p) {
    float2 v;
    asm("mov.b64 {%0, %1}, %2;" : "=f"(v.x), "=f"(v.y) : "l"(p));
    return v;
}

// Single-level stencil: lane l = (y=l>>3, x=l&7) owns vA=v(2y,x), vB=v(2y+1,x).
// Every halo tap is ONE shuffle of the original vA/vB (10 independent shfls,
// shuffle critical path = 1 level), boundary zeros applied post-shuffle:
//   A north row (2y-1) = vB of lane-8  (cols via lane-9/-8/-7)
//   B south row (2y+2) = vA of lane+8  (cols via lane+7/+8/+9)
//   mid rows W/E       = vA/vB of lane+-1
// fv[12] = {NW,N,NE, WA,vA,EA, WB,vB,EB, SW,S,SE};
// pixel A tap k uses fv[k], pixel B tap k uses fv[k+3].
__device__ __forceinline__ void stencil10(float vA, float vB,
                                          int lNW, int lN, int lNE,
                                          int lW, int lE,
                                          int lSW, int lS, int lSE,
                                          bool hn, bool hs, bool hw, bool he,
                                          float* fv) {
    const unsigned m = 0xffffffffu;
    float tNW = __shfl_sync(m, vB, lNW);
    float tN  = __shfl_sync(m, vB, lN);
    float tNE = __shfl_sync(m, vB, lNE);
    float tWA = __shfl_sync(m, vA, lW);
    float tEA = __shfl_sync(m, vA, lE);
    float tWB = __shfl_sync(m, vB, lW);
    float tEB = __shfl_sync(m, vB, lE);
    float tSW = __shfl_sync(m, vA, lSW);
    float tS  = __shfl_sync(m, vA, lS);
    float tSE = __shfl_sync(m, vA, lSE);
    fv[0] = (hn && hw) ? tNW : 0.f;
    fv[1] = hn ? tN : 0.f;
    fv[2] = (hn && he) ? tNE : 0.f;
    fv[3] = hw ? tWA : 0.f;
    fv[4] = vA;
    fv[5] = he ? tEA : 0.f;
    fv[6] = hw ? tWB : 0.f;
    fv[7] = vB;
    fv[8] = he ? tEB : 0.f;
    fv[9] = (hs && hw) ? tSW : 0.f;
    fv[10] = hs ? tS : 0.f;
    fv[11] = (hs && he) ? tSE : 0.f;
}

// R9 structure (the 57.8us kernel) with ONLY the stencil swapped to the
// single-level version: one warp per image, all 45 packed weights in
// registers, k-outer accumulation, half final round, NWARP=12.
__global__ __launch_bounds__(NWARP * 32)
void vin_kernel(const float* __restrict__ S,
                const float* __restrict__ Wh,
                const float* __restrict__ bh,
                const float* __restrict__ Wr,
                const float* __restrict__ Wq,
                const float* __restrict__ w,
                const float* __restrict__ Wfc,
                float* __restrict__ out, int B) {
    __shared__ float sweff[10];
    __shared__ u64 wsh[45];    // packed transition weights {w[2c2][k], w[2c2+1][k]}
    __shared__ u64 wqsh[45];   // packed Wq, same layout
    __shared__ float sfc[80];  // Wfc[8][10]

    const int tid = threadIdx.x;
    const int warp = tid >> 5;
    const int lane = tid & 31;

    // One-time staging of packed weights + FC head
    if (tid < 45) {
        const int c2 = tid / 9, k = tid % 9;
        wsh[tid] = pack2(__ldg(&w[(2 * c2) * 9 + k]),
                         __ldg(&w[(2 * c2 + 1) * 9 + k]));
    } else if (tid < 90) {
        const int t = tid - 45;
        const int c2 = t / 9, k = t % 9;
        wqsh[t] = pack2(__ldg(&Wq[(2 * c2) * 9 + k]),
                        __ldg(&Wq[(2 * c2 + 1) * 9 + k]));
    } else if (tid < 170) {
        sfc[tid - 90] = __ldg(&Wfc[tid - 90]);
    }
    // weff: collapse 150-ch hidden conv + 1x1 readout (warp j -> output j)
    if (warp < 10) {
        float acc = 0.f;
        for (int c = lane; c < LH; c += 32) {
            float x = (warp < 9) ? __ldg(&Wh[c * 9 + warp]) : __ldg(&bh[c]);
            acc = fmaf(__ldg(&Wr[c]), x, acc);
        }
#pragma unroll
        for (int off = 16; off >= 1; off >>= 1)
            acc += __shfl_xor_sync(0xffffffffu, acc, off);
        if (lane == 0) sweff[warp] = acc;
    }
    __syncthreads();

    const int b = blockIdx.x * NWARP + warp;
    if (b >= B) return;                    // warp-uniform; no syncs below
    const float* Sb = S + (long long)b * 66;

    const int y0 = lane >> 3, x0 = lane & 7;
    const int lNW = (lane + 23) & 31, lN = (lane + 24) & 31, lNE = (lane + 25) & 31;
    const int lW = (lane + 31) & 31, lE = (lane + 1) & 31;
    const int lSW = (lane + 7) & 31, lS = (lane + 8) & 31, lSE = (lane + 9) & 31;
    const bool hn = (y0 != 0), hs = (y0 != 3), hw = (x0 != 0), he = (x0 != 7);

    // Per-warp register copy of packed transition weights (broadcast LDS, once)
    u64 wp[45];
#pragma unroll
    for (int i = 0; i < 45; ++i) wp[i] = wsh[i];

    // X in registers: vA = row 2y, vB = row 2y+1 of column x
    float vA = Sb[16 * y0 + x0];
    float vB = Sb[16 * y0 + 8 + x0];
    const int s1i = (int)Sb[64];
    const int s2i = (int)Sb[65];

    float fv[12];

    // r = conv(X, W_eff, pad=1) + b_eff
    stencil10(vA, vB, lNW, lN, lNE, lW, lE, lSW, lS, lSE, hn, hs, hw, he, fv);
    float r0 = sweff[9], r1 = r0;
#pragma unroll
    for (int k = 0; k < 9; ++k) {
        r0 = fmaf(sweff[k], fv[k], r0);
        r1 = fmaf(sweff[k], fv[k + 3], r1);
    }

    // qr[c] = conv(r, Wq[c], pad=1)  (loop-invariant, channel-packed, k-outer)
    u64 qr0p[5], qr1p[5];
    stencil10(r0, r1, lNW, lN, lNE, lW, lE, lSW, lS, lSE, hn, hs, hw, he, fv);
#pragma unroll
    for (int k = 0; k < 9; ++k) {
        const u64 s0 = splat2(fv[k]);
        const u64 s1 = splat2(fv[k + 3]);
#pragma unroll
        for (int c2 = 0; c2 < 5; ++c2) {
            const u64 wq = wqsh[c2 * 9 + k];          // broadcast LDS, one-time
            qr0p[c2] = (k == 0) ? fma2(wq, s0, 0ull) : fma2(wq, s0, qr0p[c2]);
            qr1p[c2] = (k == 0) ? fma2(wq, s1, 0ull) : fma2(wq, s1, qr1p[c2]);
        }
    }

    // v = max_c qr
    {
        float2 t0 = unpack2(qr0p[0]), t1 = unpack2(qr1p[0]);
        vA = fmaxf(t0.x, t0.y); vB = fmaxf(t1.x, t1.y);
#pragma unroll
        for (int c2 = 1; c2 < 5; ++c2) {
            t0 = unpack2(qr0p[c2]); t1 = unpack2(qr1p[c2]);
            vA = fmaxf(vA, fmaxf(t0.x, t0.y));
            vB = fmaxf(vB, fmaxf(t1.x, t1.y));
        }
    }

    // K-1 = 9 sweeps: v <- max_c( qr[c] + conv(v, w[c]) ), all in registers
#pragma unroll 1
    for (int it = 0; it < KI - 1; ++it) {
        stencil10(vA, vB, lNW, lN, lNE, lW, lE, lSW, lS, lSE, hn, hs, hw, he, fv);
        u64 a0[5], a1[5];
#pragma unroll
        for (int k = 0; k < 9; ++k) {
            const u64 s0 = splat2(fv[k]);
            const u64 s1 = splat2(fv[k + 3]);
#pragma unroll
            for (int c2 = 0; c2 < 5; ++c2) {
                const u64 wk = wp[c2 * 9 + k];
                a0[c2] = (k == 0) ? fma2(wk, s0, qr0p[c2])
                                  : fma2(wk, s0, a0[c2]);
                a1[c2] = (k == 0) ? fma2(wk, s1, qr1p[c2])
                                  : fma2(wk, s1, a1[c2]);
            }
        }
        float2 t0 = unpack2(a0[0]), t1 = unpack2(a1[0]);
        float m0 = fmaxf(t0.x, t0.y), m1 = fmaxf(t1.x, t1.y);
#pragma unroll
        for (int c2 = 1; c2 < 5; ++c2) {
            t0 = unpack2(a0[c2]); t1 = unpack2(a1[c2]);
            m0 = fmaxf(m0, fmaxf(t0.x, t0.y));
            m1 = fmaxf(m1, fmaxf(t1.x, t1.y));
        }
        vA = m0; vB = m1;
    }

    // Final q only for the half containing the selected pixel
    // (s1 parity is per-image => warp-uniform branch). 45 FFMA2.
    stencil10(vA, vB, lNW, lN, lNE, lW, lE, lSW, lS, lSE, hn, hs, hw, he, fv);
    u64 acc[5];
    if (s1i & 1) {      // pixel in B half: taps fv[k+3], base qr1p
#pragma unroll
        for (int k = 0; k < 9; ++k) {
            const u64 s1 = splat2(fv[k + 3]);
#pragma unroll
            for (int c2 = 0; c2 < 5; ++c2)
                acc[c2] = (k == 0) ? fma2(wp[c2 * 9], s1, qr1p[c2])
                                   : fma2(wp[c2 * 9 + k], s1, acc[c2]);
        }
    } else {            // pixel in A half: taps fv[k], base qr0p
#pragma unroll
        for (int k = 0; k < 9; ++k) {
            const u64 s0 = splat2(fv[k]);
#pragma unroll
            for (int c2 = 0; c2 < 5; ++c2)
                acc[c2] = (k == 0) ? fma2(wp[c2 * 9], s0, qr0p[c2])
                                   : fma2(wp[c2 * 9 + k], s0, acc[c2]);
        }
    }

    // Selected pixel (s1=row, s2=col) lives in lane (s1>>1)*8 + s2.
    const int lsel = (s1i >> 1) * 8 + s2i;
    if (lane == lsel) {
        float lg[8];
#pragma unroll
        for (int j = 0; j < 8; ++j) lg[j] = 0.f;
#pragma unroll
        for (int c2 = 0; c2 < 5; ++c2) {
            const float2 q = unpack2(acc[c2]);
#pragma unroll
            for (int j = 0; j < 8; ++j) {
                lg[j] = fmaf(q.x, sfc[j * 10 + 2 * c2], lg[j]);
                lg[j] = fmaf(q.y, sfc[j * 10 + 2 * c2 + 1], lg[j]);
            }
        }
        float4* o4 = (float4*)(out + (long long)b * 8);
        o4[0] = make_float4(lg[0], lg[1], lg[2], lg[3]);
        o4[1] = make_float4(lg[4], lg[5], lg[6], lg[7]);
    }
}

extern "C" void kernel_launch(void* const* d_in, const int* in_sizes, int n_in,
                              void* d_out, int out_size) {
    const float* S   = (const float*)d_in[0];
    const float* Wh  = (const float*)d_in[1];
    const float* bh  = (const float*)d_in[2];
    const float* Wr  = (const float*)d_in[3];
    const float* Wq  = (const float*)d_in[4];
    const float* w   = (const float*)d_in[5];
    const float* Wfc = (const float*)d_in[6];
    float* out = (float*)d_out;

    const int B = in_sizes[0] / 66;
    const int grid = (B + NWARP - 1) / NWARP;
    vin_kernel<<<grid, NWARP * 32>>>(S, Wh, bh, Wr, Wq, w, Wfc, out, B);
}

// round 12
// speedup vs baseline: 1.2077x; 1.1323x over previous
#include <cuda_runtime.h>

typedef unsigned long long u64;

#define LH 150
#define KI 10
#define NWARP 4

__device__ float g_weff[10];
__device__ u64   g_wp[45];    // packed transition weights {w[2c2][k], w[2c2+1][k]}
__device__ u64   g_wq[45];    // packed Wq, same layout
__device__ u64   g_fcp[40];   // packed Wfc rows: {Wfc[j][2c2], Wfc[j][2c2+1]}

// ---- packed f32x2 helpers -------------------------------------------------
__device__ __forceinline__ u64 fma2(u64 a, u64 b, u64 c) {
    u64 d;
    asm("fma.rn.f32x2 %0, %1, %2, %3;" : "=l"(d) : "l"(a), "l"(b), "l"(c));
    return d;
}
__device__ __forceinline__ u64 pack2(float lo, float hi) {
    u64 r;
    asm("mov.b64 %0, {%1, %2};" : "=l"(r) : "f"(lo), "f"(hi));
    return r;
}
__device__ __forceinline__ u64 splat2(float x) {
    u64 r;
    asm("mov.b64 %0, {%1, %1};" : "=l"(r) : "f"(x));
    return r;
}
__device__ __forceinline__ float2 unpack2(u64 p) {
    float2 v;
    asm("mov.b64 {%0, %1}, %2;" : "=f"(v.x), "=f"(v.y) : "l"(p));
    return v;
}

// One-time prep: weff collapse + weight packing into device globals.
__global__ void prep_kernel(const float* __restrict__ Wh,
                            const float* __restrict__ bh,
                            const float* __restrict__ Wr,
                            const float* __restrict__ Wq,
                            const float* __restrict__ w,
                            const float* __restrict__ Wfc) {
    const int tid = threadIdx.x;
    const int warp = tid >> 5;
    const int lane = tid & 31;

    if (tid < 45) {
        const int c2 = tid / 9, k = tid % 9;
        g_wp[tid] = pack2(w[(2 * c2) * 9 + k], w[(2 * c2 + 1) * 9 + k]);
    } else if (tid < 90) {
        const int t = tid - 45;
        const int c2 = t / 9, k = t % 9;
        g_wq[t] = pack2(Wq[(2 * c2) * 9 + k], Wq[(2 * c2 + 1) * 9 + k]);
    } else if (tid < 130) {
        const int t = tid - 90;
        const int j = t / 5, c2 = t % 5;
        g_fcp[t] = pack2(Wfc[j * 10 + 2 * c2], Wfc[j * 10 + 2 * c2 + 1]);
    }
    // weff: warp j produces output j (j<9: 3x3 tap, j==9: bias)
    float acc = 0.f;
    for (int c = lane; c < LH; c += 32) {
        float x = (warp < 9) ? Wh[c * 9 + warp] : bh[c];
        acc = fmaf(Wr[c], x, acc);
    }
#pragma unroll
    for (int off = 16; off >= 1; off >>= 1)
        acc += __shfl_xor_sync(0xffffffffu, acc, off);
    if (lane == 0) g_weff[warp] = acc;
}

// Single-level stencil (proven): lane l = (y=l>>3, x=l&7) owns vA=v(2y,x),
// vB=v(2y+1,x). 10 unconditional shuffles of the ORIGINAL vA/vB; boundary
// zeros applied post-shuffle. fv[12] = {NW,N,NE, WA,vA,EA, WB,vB,EB, SW,S,SE};
// pixel A tap k uses fv[k], pixel B tap k uses fv[k+3].
__device__ __forceinline__ void stencil10(float vA, float vB,
                                          int lNW, int lN, int lNE,
                                          int lW, int lE,
                                          int lSW, int lS, int lSE,
                                          bool hn, bool hs, bool hw, bool he,
                                          float* fv) {
    const unsigned m = 0xffffffffu;
    float tNW = __shfl_sync(m, vB, lNW);
    float tN  = __shfl_sync(m, vB, lN);
    float tNE = __shfl_sync(m, vB, lNE);
    float tWA = __shfl_sync(m, vA, lW);
    float tEA = __shfl_sync(m, vA, lE);
    float tWB = __shfl_sync(m, vB, lW);
    float tEB = __shfl_sync(m, vB, lE);
    float tSW = __shfl_sync(m, vA, lSW);
    float tS  = __shfl_sync(m, vA, lS);
    float tSE = __shfl_sync(m, vA, lSE);
    fv[0] = (hn && hw) ? tNW : 0.f;
    fv[1] = hn ? tN : 0.f;
    fv[2] = (hn && he) ? tNE : 0.f;
    fv[3] = hw ? tWA : 0.f;
    fv[4] = vA;
    fv[5] = he ? tEA : 0.f;
    fv[6] = hw ? tWB : 0.f;
    fv[7] = vB;
    fv[8] = he ? tEB : 0.f;
    fv[9] = (hs && hw) ? tSW : 0.f;
    fv[10] = hs ? tS : 0.f;
    fv[11] = (hs && he) ? tSE : 0.f;
}

// One warp per image. NO shared memory, NO __syncthreads: all constants come
// from device globals (L2-hot broadcast LDG). 128-thread blocks, 3 blocks/SM
// concurrent -> fine-grained tail; weights register-resident per warp.
__global__ __launch_bounds__(NWARP * 32, 3)
void vin_kernel(const float* __restrict__ S,
                float* __restrict__ out, int B) {
    const int tid = threadIdx.x;
    const int warp = tid >> 5;
    const int lane = tid & 31;

    const int b = blockIdx.x * NWARP + warp;
    if (b >= B) return;
    const float* Sb = S + (long long)b * 66;

    const int y0 = lane >> 3, x0 = lane & 7;
    const int lNW = (lane + 23) & 31, lN = (lane + 24) & 31, lNE = (lane + 25) & 31;
    const int lW = (lane + 31) & 31, lE = (lane + 1) & 31;
    const int lSW = (lane + 7) & 31, lS = (lane + 8) & 31, lSE = (lane + 9) & 31;
    const bool hn = (y0 != 0), hs = (y0 != 3), hw = (x0 != 0), he = (x0 != 7);

    // Register-resident packed transition weights (45 independent LDG.64,
    // L2-hot broadcast; overlapped with the S loads below)
    u64 wp[45];
#pragma unroll
    for (int i = 0; i < 45; ++i) wp[i] = __ldg(&g_wp[i]);

    // X in registers: vA = row 2y, vB = row 2y+1 of column x
    float vA = Sb[16 * y0 + x0];
    float vB = Sb[16 * y0 + 8 + x0];
    const int s1i = (int)Sb[64];
    const int s2i = (int)Sb[65];

    float fv[12];

    // r = conv(X, W_eff, pad=1) + b_eff
    stencil10(vA, vB, lNW, lN, lNE, lW, lE, lSW, lS, lSE, hn, hs, hw, he, fv);
    float r0 = __ldg(&g_weff[9]), r1 = r0;
#pragma unroll
    for (int k = 0; k < 9; ++k) {
        const float wk = __ldg(&g_weff[k]);
        r0 = fmaf(wk, fv[k], r0);
        r1 = fmaf(wk, fv[k + 3], r1);
    }

    // qr[c] = conv(r, Wq[c], pad=1)  (loop-invariant, channel-packed, k-outer)
    u64 qr0p[5], qr1p[5];
    stencil10(r0, r1, lNW, lN, lNE, lW, lE, lSW, lS, lSE, hn, hs, hw, he, fv);
#pragma unroll
    for (int k = 0; k < 9; ++k) {
        const u64 s0 = splat2(fv[k]);
        const u64 s1 = splat2(fv[k + 3]);
#pragma unroll
        for (int c2 = 0; c2 < 5; ++c2) {
            const u64 wq = __ldg(&g_wq[c2 * 9 + k]);  // one-time, L2-hot
            qr0p[c2] = (k == 0) ? fma2(wq, s0, 0ull) : fma2(wq, s0, qr0p[c2]);
            qr1p[c2] = (k == 0) ? fma2(wq, s1, 0ull) : fma2(wq, s1, qr1p[c2]);
        }
    }

    // v = max_c qr
    {
        float2 t0 = unpack2(qr0p[0]), t1 = unpack2(qr1p[0]);
        vA = fmaxf(t0.x, t0.y); vB = fmaxf(t1.x, t1.y);
#pragma unroll
        for (int c2 = 1; c2 < 5; ++c2) {
            t0 = unpack2(qr0p[c2]); t1 = unpack2(qr1p[c2]);
            vA = fmaxf(vA, fmaxf(t0.x, t0.y));
            vB = fmaxf(vB, fmaxf(t1.x, t1.y));
        }
    }

    // K-1 = 9 sweeps: v <- max_c( qr[c] + conv(v, w[c]) ), all in registers
#pragma unroll 3
    for (int it = 0; it < KI - 1; ++it) {
        stencil10(vA, vB, lNW, lN, lNE, lW, lE, lSW, lS, lSE, hn, hs, hw, he, fv);
        u64 a0[5], a1[5];
#pragma unroll
        for (int k = 0; k < 9; ++k) {
            const u64 s0 = splat2(fv[k]);
            const u64 s1 = splat2(fv[k + 3]);
#pragma unroll
            for (int c2 = 0; c2 < 5; ++c2) {
                const u64 wk = wp[c2 * 9 + k];
                a0[c2] = (k == 0) ? fma2(wk, s0, qr0p[c2])
                                  : fma2(wk, s0, a0[c2]);
                a1[c2] = (k == 0) ? fma2(wk, s1, qr1p[c2])
                                  : fma2(wk, s1, a1[c2]);
            }
        }
        float2 t0 = unpack2(a0[0]), t1 = unpack2(a1[0]);
        float m0 = fmaxf(t0.x, t0.y), m1 = fmaxf(t1.x, t1.y);
#pragma unroll
        for (int c2 = 1; c2 < 5; ++c2) {
            t0 = unpack2(a0[c2]); t1 = unpack2(a1[c2]);
            m0 = fmaxf(m0, fmaxf(t0.x, t0.y));
            m1 = fmaxf(m1, fmaxf(t1.x, t1.y));
        }
        vA = m0; vB = m1;
    }

    // Final q only for the half containing the selected pixel
    // (s1 parity is per-image => warp-uniform branch). 45 FFMA2.
    stencil10(vA, vB, lNW, lN, lNE, lW, lE, lSW, lS, lSE, hn, hs, hw, he, fv);
    u64 acc[5];
    if (s1i & 1) {      // pixel in B half: taps fv[k+3], base qr1p
#pragma unroll
        for (int k = 0; k < 9; ++k) {
            const u64 s1 = splat2(fv[k + 3]);
#pragma unroll
            for (int c2 = 0; c2 < 5; ++c2)
                acc[c2] = (k == 0) ? fma2(wp[c2 * 9], s1, qr1p[c2])
                                   : fma2(wp[c2 * 9 + k], s1, acc[c2]);
        }
    } else {            // pixel in A half: taps fv[k], base qr0p
#pragma unroll
        for (int k = 0; k < 9; ++k) {
            const u64 s0 = splat2(fv[k]);
#pragma unroll
            for (int c2 = 0; c2 < 5; ++c2)
                acc[c2] = (k == 0) ? fma2(wp[c2 * 9], s0, qr0p[c2])
                                   : fma2(wp[c2 * 9 + k], s0, acc[c2]);
        }
    }

    // Selected pixel lives in lane (s1>>1)*8 + s2; packed FC head:
    // lg[j] = horizontal_sum( sum_c2 acc[c2]*fcp[j][c2] )
    const int lsel = (s1i >> 1) * 8 + s2i;
    if (lane == lsel) {
        float lg[8];
#pragma unroll
        for (int j = 0; j < 8; ++j) {
            u64 la = 0ull;
#pragma unroll
            for (int c2 = 0; c2 < 5; ++c2)
                la = fma2(acc[c2], __ldg(&g_fcp[j * 5 + c2]), la);
            const float2 t = unpack2(la);
            lg[j] = t.x + t.y;
        }
        float4* o4 = (float4*)(out + (long long)b * 8);
        o4[0] = make_float4(lg[0], lg[1], lg[2], lg[3]);
        o4[1] = make_float4(lg[4], lg[5], lg[6], lg[7]);
    }
}

extern "C" void kernel_launch(void* const* d_in, const int* in_sizes, int n_in,
                              void* d_out, int out_size) {
    const float* S   = (const float*)d_in[0];
    const float* Wh  = (const float*)d_in[1];
    const float* bh  = (const float*)d_in[2];
    const float* Wr  = (const float*)d_in[3];
    const float* Wq  = (const float*)d_in[4];
    const float* w   = (const float*)d_in[5];
    const float* Wfc = (const float*)d_in[6];
    float* out = (float*)d_out;

    const int B = in_sizes[0] / 66;
    prep_kernel<<<1, 320>>>(Wh, bh, Wr, Wq, w, Wfc);
    const int grid = (B + NWARP - 1) / NWARP;
    vin_kernel<<<grid, NWARP * 32>>>(S, out, B);
}

// round 13
// speedup vs baseline: 1.2482x; 1.0335x over previous
#include <cuda_runtime.h>

typedef unsigned long long u64;

#define LH 150
#define KI 10
#define NWARP 4

__device__ float g_weff[10];
__device__ u64   g_wp[45];    // packed transition weights {w[2c2][k], w[2c2+1][k]}
__device__ u64   g_wq[45];    // packed Wq, same layout
__device__ u64   g_fcp[40];   // packed Wfc rows: {Wfc[j][2c2], Wfc[j][2c2+1]}

// ---- packed f32x2 helpers -------------------------------------------------
__device__ __forceinline__ u64 fma2(u64 a, u64 b, u64 c) {
    u64 d;
    asm("fma.rn.f32x2 %0, %1, %2, %3;" : "=l"(d) : "l"(a), "l"(b), "l"(c));
    return d;
}
__device__ __forceinline__ u64 pack2(float lo, float hi) {
    u64 r;
    asm("mov.b64 %0, {%1, %2};" : "=l"(r) : "f"(lo), "f"(hi));
    return r;
}
__device__ __forceinline__ u64 splat2(float x) {
    u64 r;
    asm("mov.b64 %0, {%1, %1};" : "=l"(r) : "f"(x));
    return r;
}
__device__ __forceinline__ float2 unpack2(u64 p) {
    float2 v;
    asm("mov.b64 {%0, %1}, %2;" : "=f"(v.x), "=f"(v.y) : "l"(p));
    return v;
}

// One-time prep: weff collapse + weight packing into device globals.
__global__ void prep_kernel(const float* __restrict__ Wh,
                            const float* __restrict__ bh,
                            const float* __restrict__ Wr,
                            const float* __restrict__ Wq,
                            const float* __restrict__ w,
                            const float* __restrict__ Wfc) {
    const int tid = threadIdx.x;
    const int warp = tid >> 5;
    const int lane = tid & 31;

    if (tid < 45) {
        const int c2 = tid / 9, k = tid % 9;
        g_wp[tid] = pack2(w[(2 * c2) * 9 + k], w[(2 * c2 + 1) * 9 + k]);
    } else if (tid < 90) {
        const int t = tid - 45;
        const int c2 = t / 9, k = t % 9;
        g_wq[t] = pack2(Wq[(2 * c2) * 9 + k], Wq[(2 * c2 + 1) * 9 + k]);
    } else if (tid < 130) {
        const int t = tid - 90;
        const int j = t / 5, c2 = t % 5;
        g_fcp[t] = pack2(Wfc[j * 10 + 2 * c2], Wfc[j * 10 + 2 * c2 + 1]);
    }
    // weff: warp j produces output j (j<9: 3x3 tap, j==9: bias)
    float acc = 0.f;
    for (int c = lane; c < LH; c += 32) {
        float x = (warp < 9) ? Wh[c * 9 + warp] : bh[c];
        acc = fmaf(Wr[c], x, acc);
    }
#pragma unroll
    for (int off = 16; off >= 1; off >>= 1)
        acc += __shfl_xor_sync(0xffffffffu, acc, off);
    if (lane == 0) g_weff[warp] = acc;
}

// Single-level stencil (proven): lane l = (y=l>>3, x=l&7) owns vA=v(2y,x),
// vB=v(2y+1,x). 10 unconditional shuffles of the ORIGINAL vA/vB; boundary
// zeros applied post-shuffle. fv[12] = {NW,N,NE, WA,vA,EA, WB,vB,EB, SW,S,SE};
// pixel A tap k uses fv[k], pixel B tap k uses fv[k+3].
__device__ __forceinline__ void stencil10(float vA, float vB,
                                          int lNW, int lN, int lNE,
                                          int lW, int lE,
                                          int lSW, int lS, int lSE,
                                          bool hn, bool hs, bool hw, bool he,
                                          float* fv) {
    const unsigned m = 0xffffffffu;
    float tNW = __shfl_sync(m, vB, lNW);
    float tN  = __shfl_sync(m, vB, lN);
    float tNE = __shfl_sync(m, vB, lNE);
    float tWA = __shfl_sync(m, vA, lW);
    float tEA = __shfl_sync(m, vA, lE);
    float tWB = __shfl_sync(m, vB, lW);
    float tEB = __shfl_sync(m, vB, lE);
    float tSW = __shfl_sync(m, vA, lSW);
    float tS  = __shfl_sync(m, vA, lS);
    float tSE = __shfl_sync(m, vA, lSE);
    fv[0] = (hn && hw) ? tNW : 0.f;
    fv[1] = hn ? tN : 0.f;
    fv[2] = (hn && he) ? tNE : 0.f;
    fv[3] = hw ? tWA : 0.f;
    fv[4] = vA;
    fv[5] = he ? tEA : 0.f;
    fv[6] = hw ? tWB : 0.f;
    fv[7] = vB;
    fv[8] = he ? tEB : 0.f;
    fv[9] = (hs && hw) ? tSW : 0.f;
    fv[10] = hs ? tS : 0.f;
    fv[11] = (hs && he) ? tSE : 0.f;
}

// One warp per image; no smem, no block syncs. c2<3 weights in registers
// (54 regs); c2 in {3,4} weights re-read per round via constant-offset LDG.64
// from an opaque uniform pointer (L1/L2-hot broadcast, no index ALU) so that
// regs fit 128 -> 4 blocks/SM (16 warps).
__global__ __launch_bounds__(NWARP * 32, 4)
void vin_kernel(const float* __restrict__ S,
                float* __restrict__ out, int B) {
    const int tid = threadIdx.x;
    const int warp = tid >> 5;
    const int lane = tid & 31;

    const int b = blockIdx.x * NWARP + warp;
    if (b >= B) return;
    const float* Sb = S + (long long)b * 66;

    const int y0 = lane >> 3, x0 = lane & 7;
    const int lNW = (lane + 23) & 31, lN = (lane + 24) & 31, lNE = (lane + 25) & 31;
    const int lW = (lane + 31) & 31, lE = (lane + 1) & 31;
    const int lSW = (lane + 7) & 31, lS = (lane + 8) & 31, lSE = (lane + 9) & 31;
    const bool hn = (y0 != 0), hs = (y0 != 3), hw = (x0 != 0), he = (x0 != 7);

    // Register-resident packed weights for c2 = 0..2 only (54 regs)
    u64 wreg[27];
#pragma unroll
    for (int i = 0; i < 27; ++i) wreg[i] = __ldg(&g_wp[i]);

    // X in registers: vA = row 2y, vB = row 2y+1 of column x
    float vA = Sb[16 * y0 + x0];
    float vB = Sb[16 * y0 + 8 + x0];
    const int s1i = (int)Sb[64];
    const int s2i = (int)Sb[65];

    float fv[12];

    // r = conv(X, W_eff, pad=1) + b_eff
    stencil10(vA, vB, lNW, lN, lNE, lW, lE, lSW, lS, lSE, hn, hs, hw, he, fv);
    float r0 = __ldg(&g_weff[9]), r1 = r0;
#pragma unroll
    for (int k = 0; k < 9; ++k) {
        const float wk = __ldg(&g_weff[k]);
        r0 = fmaf(wk, fv[k], r0);
        r1 = fmaf(wk, fv[k + 3], r1);
    }

    // qr[c] = conv(r, Wq[c], pad=1)  (loop-invariant, channel-packed, k-outer)
    u64 qr0p[5], qr1p[5];
    stencil10(r0, r1, lNW, lN, lNE, lW, lE, lSW, lS, lSE, hn, hs, hw, he, fv);
#pragma unroll
    for (int k = 0; k < 9; ++k) {
        const u64 s0 = splat2(fv[k]);
        const u64 s1 = splat2(fv[k + 3]);
#pragma unroll
        for (int c2 = 0; c2 < 5; ++c2) {
            const u64 wq = __ldg(&g_wq[c2 * 9 + k]);  // one-time, L2-hot
            qr0p[c2] = (k == 0) ? fma2(wq, s0, 0ull) : fma2(wq, s0, qr0p[c2]);
            qr1p[c2] = (k == 0) ? fma2(wq, s1, 0ull) : fma2(wq, s1, qr1p[c2]);
        }
    }

    // v = max_c qr
    {
        float2 t0 = unpack2(qr0p[0]), t1 = unpack2(qr1p[0]);
        vA = fmaxf(t0.x, t0.y); vB = fmaxf(t1.x, t1.y);
#pragma unroll
        for (int c2 = 1; c2 < 5; ++c2) {
            t0 = unpack2(qr0p[c2]); t1 = unpack2(qr1p[c2]);
            vA = fmaxf(vA, fmaxf(t0.x, t0.y));
            vB = fmaxf(vB, fmaxf(t1.x, t1.y));
        }
    }

    // K-1 = 9 sweeps: v <- max_c( qr[c] + conv(v, w[c]) )
#pragma unroll 1
    for (int it = 0; it < KI - 1; ++it) {
        // Opaque pointer: c2={3,4} weight loads stay per-round LDG.64 with
        // constant offsets (not hoisted into registers).
        const u64* wdy = g_wp + 27;
        asm("" : "+l"(wdy));
        stencil10(vA, vB, lNW, lN, lNE, lW, lE, lSW, lS, lSE, hn, hs, hw, he, fv);
        u64 a0[5], a1[5];
#pragma unroll
        for (int k = 0; k < 9; ++k) {
            const u64 s0 = splat2(fv[k]);
            const u64 s1 = splat2(fv[k + 3]);
            const u64 w3 = __ldg(&wdy[k]);        // c2=3, tap k
            const u64 w4 = __ldg(&wdy[9 + k]);    // c2=4, tap k
#pragma unroll
            for (int c2 = 0; c2 < 3; ++c2) {
                const u64 wk = wreg[c2 * 9 + k];
                a0[c2] = (k == 0) ? fma2(wk, s0, qr0p[c2]) : fma2(wk, s0, a0[c2]);
                a1[c2] = (k == 0) ? fma2(wk, s1, qr1p[c2]) : fma2(wk, s1, a1[c2]);
            }
            a0[3] = (k == 0) ? fma2(w3, s0, qr0p[3]) : fma2(w3, s0, a0[3]);
            a1[3] = (k == 0) ? fma2(w3, s1, qr1p[3]) : fma2(w3, s1, a1[3]);
            a0[4] = (k == 0) ? fma2(w4, s0, qr0p[4]) : fma2(w4, s0, a0[4]);
            a1[4] = (k == 0) ? fma2(w4, s1, qr1p[4]) : fma2(w4, s1, a1[4]);
        }
        float2 t0 = unpack2(a0[0]), t1 = unpack2(a1[0]);
        float m0 = fmaxf(t0.x, t0.y), m1 = fmaxf(t1.x, t1.y);
#pragma unroll
        for (int c2 = 1; c2 < 5; ++c2) {
            t0 = unpack2(a0[c2]); t1 = unpack2(a1[c2]);
            m0 = fmaxf(m0, fmaxf(t0.x, t0.y));
            m1 = fmaxf(m1, fmaxf(t1.x, t1.y));
        }
        vA = m0; vB = m1;
    }

    // Final q only for the half containing the selected pixel (warp-uniform).
    stencil10(vA, vB, lNW, lN, lNE, lW, lE, lSW, lS, lSE, hn, hs, hw, he, fv);
    u64 acc[5];
    {
        const u64* wdy = g_wp + 27;
        asm("" : "+l"(wdy));
        const int off = (s1i & 1) ? 3 : 0;     // B half taps fv[k+3]
        const u64* qrp = (s1i & 1) ? qr1p : qr0p;
#pragma unroll
        for (int k = 0; k < 9; ++k) {
            const u64 s = splat2(fv[k + off]);
            const u64 w3 = __ldg(&wdy[k]);
            const u64 w4 = __ldg(&wdy[9 + k]);
#pragma unroll
            for (int c2 = 0; c2 < 3; ++c2)
                acc[c2] = (k == 0) ? fma2(wreg[c2 * 9], s, qrp[c2])
                                   : fma2(wreg[c2 * 9 + k], s, acc[c2]);
            acc[3] = (k == 0) ? fma2(w3, s, qrp[3]) : fma2(w3, s, acc[3]);
            acc[4] = (k == 0) ? fma2(w4, s, qrp[4]) : fma2(w4, s, acc[4]);
        }
    }

    // Selected pixel lives in lane (s1>>1)*8 + s2; packed FC head.
    const int lsel = (s1i >> 1) * 8 + s2i;
    if (lane == lsel) {
        float lg[8];
#pragma unroll
        for (int j = 0; j < 8; ++j) {
            u64 la = 0ull;
#pragma unroll
            for (int c2 = 0; c2 < 5; ++c2)
                la = fma2(acc[c2], __ldg(&g_fcp[j * 5 + c2]), la);
            const float2 t = unpack2(la);
            lg[j] = t.x + t.y;
        }
        float4* o4 = (float4*)(out + (long long)b * 8);
        o4[0] = make_float4(lg[0], lg[1], lg[2], lg[3]);
        o4[1] = make_float4(lg[4], lg[5], lg[6], lg[7]);
    }
}

extern "C" void kernel_launch(void* const* d_in, const int* in_sizes, int n_in,
                              void* d_out, int out_size) {
    const float* S   = (const float*)d_in[0];
    const float* Wh  = (const float*)d_in[1];
    const float* bh  = (const float*)d_in[2];
    const float* Wr  = (const float*)d_in[3];
    const float* Wq  = (const float*)d_in[4];
    const float* w   = (const float*)d_in[5];
    const float* Wfc = (const float*)d_in[6];
    float* out = (float*)d_out;

    const int B = in_sizes[0] / 66;
    prep_kernel<<<1, 320>>>(Wh, bh, Wr, Wq, w, Wfc);
    const int grid = (B + NWARP - 1) / NWARP;
    vin_kernel<<<grid, NWARP * 32>>>(S, out, B);
}